// round 14
// baseline (speedup 1.0000x reference)
#include <cuda_runtime.h>
#include <cuda_fp16.h>
#include <math.h>
#include <stdint.h>

// ---------------------------------------------------------------------------
// N=100000 nodes, F=256, E=1600000.
// Layer 1: 256 -> 8 heads x 16   (HC=128)
// Layer 2: 128 -> 8 heads x 8    (HC=64)
// Layer 3:  64 -> 1 head  x 10   (HC=10), then log_softmax
// ---------------------------------------------------------------------------
#define MAXN 100000
#define MAXE 1600000

__device__ __align__(16) __half g_xp[MAXN * 128];  // transformed features (fp16)
__device__ __align__(16) float g_h [MAXN * 128];   // layer activations (fp32)
__device__ __align__(16) float g_xp3[MAXN * 16];   // layer-3 logits (fp32)
__device__ float g_asrc[MAXN * 8];
__device__ float g_adst[MAXN * 8];
__device__ int   g_srcbuf[MAXE];
__device__ int   g_dstbuf[MAXE];
__device__ int   g_deg[MAXN];          // BSS-zero at load; re-zeroed by scan
__device__ int   g_cursor[MAXN];
__device__ int   g_row[MAXN + 1];
__device__ int   g_csr[MAXE + MAXN];
__device__ int   g_bsum[1024];
__device__ int   g_boff[1024];
// Global per-head asrc maxima (ordered-uint encoded). Slots: M1=0-7, M2=8-15, M3=16.
__device__ unsigned g_gmax[17];

// ---------------------------------------------------------------------------
// PTX helpers
// ---------------------------------------------------------------------------
__device__ __forceinline__ void cp_async16(uint32_t dst, const void* src) {
    asm volatile("cp.async.cg.shared.global [%0], [%1], 16;" :: "r"(dst), "l"(src));
}
#define CP_COMMIT() asm volatile("cp.async.commit_group;")
#define CP_WAIT0()  asm volatile("cp.async.wait_group 0;")

__device__ __forceinline__ uint32_t f2tf(float f) {
    uint32_t r;
    asm("cvt.rna.tf32.f32 %0, %1;" : "=r"(r) : "f"(f));
    return r;
}

// Ordered-uint encoding: strictly monotone float -> unsigned.
__device__ __forceinline__ unsigned encf(float f) {
    unsigned b = __float_as_uint(f);
    return (b & 0x80000000u) ? ~b : (b | 0x80000000u);
}
__device__ __forceinline__ float decf(unsigned u) {
    return __uint_as_float((u & 0x80000000u) ? (u & 0x7FFFFFFFu) : ~u);
}

__device__ __forceinline__ void mma_tf32(float& d0, float& d1, float& d2, float& d3,
                                         uint32_t a0, uint32_t a1, uint32_t a2, uint32_t a3,
                                         uint32_t b0, uint32_t b1) {
    asm("mma.sync.aligned.m16n8k8.row.col.f32.tf32.tf32.f32 "
        "{%0,%1,%2,%3}, {%4,%5,%6,%7}, {%8,%9}, {%0,%1,%2,%3};"
        : "+f"(d0), "+f"(d1), "+f"(d2), "+f"(d3)
        : "r"(a0), "r"(a1), "r"(a2), "r"(a3), "r"(b0), "r"(b1));
}

// ---------------------------------------------------------------------------
// Edge conversion (dtype detect inlined) + degree histogram
// ---------------------------------------------------------------------------
__global__ void convert_hist_kernel(const void* ei, int E, int N) {
    __shared__ int s64;
    if (threadIdx.x == 0) {
        const long long* p = (const long long*)ei;
        int ok = 1;
        for (int i = 0; i < 8; i++) {
            long long v = p[i];
            if (v < 0 || v >= (long long)N) ok = 0;
        }
        s64 = ok;
    }
    __syncthreads();
    int e = blockIdx.x * blockDim.x + threadIdx.x;
    if (e >= E) return;
    int src, dst;
    if (s64) {
        const long long* p = (const long long*)ei;
        src = (int)p[e];
        dst = (int)p[(size_t)E + e];
    } else {
        const int* p = (const int*)ei;
        src = p[e];
        dst = p[(size_t)E + e];
    }
    g_srcbuf[e] = src;
    g_dstbuf[e] = dst;
    atomicAdd(&g_deg[dst], 1);
}

// ---------------------------------------------------------------------------
// Parallel exclusive scan (3 kernels) over (deg+1); seeds self loops + cursors.
// ---------------------------------------------------------------------------
__global__ void scan_blocks_kernel(int N) {
    int i = blockIdx.x * 256 + threadIdx.x;
    int v = 0;
    if (i < N) {
        v = g_deg[i] + 1;   // +1 = self loop
        g_deg[i] = 0;       // reset for next launch
    }
    int lane = threadIdx.x & 31, wid = threadIdx.x >> 5;
    int x = v;
#pragma unroll
    for (int off = 1; off < 32; off <<= 1) {
        int t = __shfl_up_sync(0xFFFFFFFFu, x, off);
        if (lane >= off) x += t;
    }
    __shared__ int wsum[8];
    if (lane == 31) wsum[wid] = x;
    __syncthreads();
    if (threadIdx.x == 0) {
        int run = 0;
#pragma unroll
        for (int w = 0; w < 8; w++) { int t = wsum[w]; wsum[w] = run; run += t; }
        g_bsum[blockIdx.x] = run;
    }
    __syncthreads();
    if (i < N) g_row[i] = x - v + wsum[wid];
}

__global__ void scan_top_kernel(int nb, int N) {
    int t = threadIdx.x;
    int v = (t < nb) ? g_bsum[t] : 0;
    int lane = t & 31, wid = t >> 5;
    int x = v;
#pragma unroll
    for (int off = 1; off < 32; off <<= 1) {
        int s = __shfl_up_sync(0xFFFFFFFFu, x, off);
        if (lane >= off) x += s;
    }
    __shared__ int wsum[32];
    if (lane == 31) wsum[wid] = x;
    __syncthreads();
    if (t == 0) {
        int run = 0;
#pragma unroll
        for (int w = 0; w < 32; w++) { int s = wsum[w]; wsum[w] = run; run += s; }
        g_row[N] = run;
    }
    __syncthreads();
    if (t < nb) g_boff[t] = x - v + wsum[wid];
}

__global__ void scan_add_seed_kernel(int N) {
    int i = blockIdx.x * 256 + threadIdx.x;
    if (i >= N) return;
    int r = g_row[i] + g_boff[i >> 8];
    g_row[i] = r;
    g_csr[r] = i;          // self loop in slot 0
    g_cursor[i] = r + 1;
}

__global__ void scatter_kernel(int E) {
    int e = blockIdx.x * blockDim.x + threadIdx.x;
    if (e < E) {
        int pos = atomicAdd(&g_cursor[g_dstbuf[e]], 1);
        g_csr[pos] = g_srcbuf[e];
    }
}

// ---------------------------------------------------------------------------
// Tensor-core GEMM (tf32 mma.sync) + fused attention logits + global asrc max.
// ---------------------------------------------------------------------------
template <int KIN, int KOUT, int H, int C, bool READ_H, int GOFF>
__global__ void gemm_mma_kernel(const float* __restrict__ Ain,
                                const float* __restrict__ W,
                                const float* __restrict__ a_s,
                                const float* __restrict__ a_d,
                                int N) {
    constexpr int BM = 128, BK = 32, BN = KOUT;
    constexpr int NT = 256;
    constexpr int SA = 36;
    constexpr int SB = BN + 8;
    constexpr int T  = KIN / BK;
    constexpr int BNW = BN / 2;
    constexpr int NTILES = BNW / 8;
    constexpr int MTILES = 2;
    constexpr int NHL = BNW / C;
    constexpr int AS_SZ = 2 * BM * SA;
    constexpr int BS_SZ = 2 * BK * SB;

    extern __shared__ float sm[];
    float* As  = sm;
    float* Bs  = sm + AS_SZ;
    float* s_as = sm + AS_SZ + BS_SZ;
    float* s_ad = s_as + BN;
    __shared__ unsigned s_enc[H];

    const float* A = READ_H ? g_h : Ain;
    int tid = threadIdx.x;
    int row0 = blockIdx.x * BM;

    for (int i = tid; i < BN; i += NT) { s_as[i] = a_s[i]; s_ad[i] = a_d[i]; }
    if (tid < H) s_enc[tid] = 0u;

    auto load_tile = [&](int t, int b) {
        int k0 = t * BK;
#pragma unroll
        for (int idx = tid; idx < BM * (BK / 4); idx += NT) {
            int m = idx >> 3, k4 = idx & 7;
            int gr = min(row0 + m, N - 1);
            cp_async16((uint32_t)__cvta_generic_to_shared(&As[b * BM * SA + m * SA + k4 * 4]),
                       &A[(size_t)gr * KIN + k0 + k4 * 4]);
        }
#pragma unroll
        for (int idx = tid; idx < BK * (BN / 4); idx += NT) {
            int k = idx / (BN / 4), n4 = idx % (BN / 4);
            cp_async16((uint32_t)__cvta_generic_to_shared(&Bs[b * BK * SB + k * SB + n4 * 4]),
                       &W[(size_t)(k0 + k) * KOUT + n4 * 4]);
        }
        CP_COMMIT();
    };

    int lane = tid & 31;
    int gid = lane >> 2, tig = lane & 3;
    int w = tid >> 5;
    int warp_n = w & 1, warp_m = w >> 1;
    int mbase = warp_m * 32;
    int nbase = warp_n * BNW;

    float acc[MTILES][NTILES][4];
#pragma unroll
    for (int mt = 0; mt < MTILES; mt++)
#pragma unroll
        for (int nt = 0; nt < NTILES; nt++)
#pragma unroll
            for (int q = 0; q < 4; q++) acc[mt][nt][q] = 0.f;

    load_tile(0, 0);
    CP_WAIT0();
    __syncthreads();

    for (int t = 0; t < T; t++) {
        if (t + 1 < T) load_tile(t + 1, (t + 1) & 1);
        int b = t & 1;
        const float* Ab = &As[b * BM * SA];
        const float* Bb = &Bs[b * BK * SB];
#pragma unroll
        for (int k8 = 0; k8 < BK / 8; k8++) {
            int kk = k8 * 8;
            uint32_t af[MTILES][4];
#pragma unroll
            for (int mt = 0; mt < MTILES; mt++) {
                const float* ar = &Ab[(mbase + mt * 16 + gid) * SA + kk + tig];
                af[mt][0] = f2tf(ar[0]);
                af[mt][1] = f2tf(ar[8 * SA]);
                af[mt][2] = f2tf(ar[4]);
                af[mt][3] = f2tf(ar[8 * SA + 4]);
            }
            uint32_t bf[NTILES][2];
#pragma unroll
            for (int nt = 0; nt < NTILES; nt++) {
                const float* br = &Bb[(kk + tig) * SB + nbase + nt * 8 + gid];
                bf[nt][0] = __float_as_uint(br[0]);
                bf[nt][1] = __float_as_uint(br[4 * SB]);
            }
#pragma unroll
            for (int mt = 0; mt < MTILES; mt++)
#pragma unroll
                for (int nt = 0; nt < NTILES; nt++)
                    mma_tf32(acc[mt][nt][0], acc[mt][nt][1], acc[mt][nt][2], acc[mt][nt][3],
                             af[mt][0], af[mt][1], af[mt][2], af[mt][3],
                             bf[nt][0], bf[nt][1]);
        }
        if (t + 1 < T) {
            CP_WAIT0();
            __syncthreads();
        }
    }

#pragma unroll
    for (int mt = 0; mt < MTILES; mt++) {
        int r0 = row0 + mbase + mt * 16 + gid;
        int r1 = r0 + 8;
        float ps0[NHL], pd0[NHL], ps1[NHL], pd1[NHL];
#pragma unroll
        for (int hl = 0; hl < NHL; hl++) { ps0[hl] = pd0[hl] = ps1[hl] = pd1[hl] = 0.f; }
#pragma unroll
        for (int nt = 0; nt < NTILES; nt++) {
            int col = nbase + nt * 8 + 2 * tig;
            int hl = (nt * 8) / C;
            float d0 = acc[mt][nt][0], d1 = acc[mt][nt][1];
            float d2 = acc[mt][nt][2], d3 = acc[mt][nt][3];
            if (r0 < N) *reinterpret_cast<__half2*>(&g_xp[(size_t)r0 * KOUT + col]) =
                __floats2half2_rn(d0, d1);
            if (r1 < N) *reinterpret_cast<__half2*>(&g_xp[(size_t)r1 * KOUT + col]) =
                __floats2half2_rn(d2, d3);
            float w0 = s_as[col], w1 = s_as[col + 1];
            float v0 = s_ad[col], v1 = s_ad[col + 1];
            ps0[hl] += d0 * w0 + d1 * w1;
            pd0[hl] += d0 * v0 + d1 * v1;
            ps1[hl] += d2 * w0 + d3 * w1;
            pd1[hl] += d2 * v0 + d3 * v1;
        }
#pragma unroll
        for (int hl = 0; hl < NHL; hl++) {
            ps0[hl] += __shfl_xor_sync(0xFFFFFFFFu, ps0[hl], 1);
            ps0[hl] += __shfl_xor_sync(0xFFFFFFFFu, ps0[hl], 2);
            pd0[hl] += __shfl_xor_sync(0xFFFFFFFFu, pd0[hl], 1);
            pd0[hl] += __shfl_xor_sync(0xFFFFFFFFu, pd0[hl], 2);
            ps1[hl] += __shfl_xor_sync(0xFFFFFFFFu, ps1[hl], 1);
            ps1[hl] += __shfl_xor_sync(0xFFFFFFFFu, ps1[hl], 2);
            pd1[hl] += __shfl_xor_sync(0xFFFFFFFFu, pd1[hl], 1);
            pd1[hl] += __shfl_xor_sync(0xFFFFFFFFu, pd1[hl], 2);
        }
        if (tig == 0) {
#pragma unroll
            for (int hl = 0; hl < NHL; hl++) {
                int head = nbase / C + hl;
                if (r0 < N) {
                    g_asrc[(size_t)r0 * H + head] = ps0[hl];
                    g_adst[(size_t)r0 * H + head] = pd0[hl];
                    atomicMax(&s_enc[head], encf(ps0[hl]));
                }
                if (r1 < N) {
                    g_asrc[(size_t)r1 * H + head] = ps1[hl];
                    g_adst[(size_t)r1 * H + head] = pd1[hl];
                    atomicMax(&s_enc[head], encf(ps1[hl]));
                }
            }
        }
    }
    __syncthreads();
    if (tid < H) atomicMax(&g_gmax[GOFF + tid], s_enc[tid]);
}

// ---------------------------------------------------------------------------
// Aggregation: warp-per-dst, single-pass (global-max bound), BATCHED logit
// loads: a warp covers 4 edges x 8 heads per step — ONE dependent
// csr->asrc chain per 4 edges (was per edge), distributed via shfl.
// ---------------------------------------------------------------------------
template <int H, int C, bool DO_ELU, int GOFF>
__global__ void aggregate_kernel(const float* __restrict__ bias, int N) {
    constexpr int HC = H * C;
    constexpr int VPL = HC / 32;
    constexpr int LPH = C / VPL;       // 4 lanes per head (both layers)
    static_assert(H == 8, "batch layout assumes 8 heads");

    int d = (blockIdx.x * blockDim.x + threadIdx.x) >> 5;
    int lane = threadIdx.x & 31;
    if (d >= N) return;
    int head = lane / LPH;             // head for the gather phase
    int b_e  = lane >> 3;              // edge slot (0..3) for the load phase
    int b_h  = lane & 7;               // head for the load phase

    float adst_b = g_adst[(size_t)d * H + b_h];
    float M = decf(g_gmax[GOFF + head]);
    float adst_h = __shfl_sync(0xFFFFFFFFu, adst_b, head);   // adst for gather head
    float em = M + adst_h;
    float m = (em > 0.f) ? em : 0.2f * em;   // >= all logits for this (dst, head)

    int lo = g_row[d], hi = g_row[d + 1];

    float s = 0.f;
    float acc[VPL];
#pragma unroll
    for (int v = 0; v < VPL; v++) acc[v] = 0.f;

    for (int base = lo; base < hi; base += 4) {
        // Load phase: one csr + one asrc load per lane covers 4 edges x 8 heads
        int j = base + b_e;
        int src_j = 0;
        float e_j = 0.f;
        if (j < hi) {
            src_j = g_csr[j];
            float e = g_asrc[(size_t)src_j * H + b_h] + adst_b;
            e_j = (e > 0.f) ? e : 0.2f * e;
        }
        int nb = min(hi - base, 4);
        // Gather phase: distribute (src, e) via shfl, then independent gathers
#pragma unroll
        for (int b = 0; b < 4; b++) {
            if (b >= nb) break;        // warp-uniform
            float e  = __shfl_sync(0xFFFFFFFFu, e_j, b * 8 + head);
            int src  = __shfl_sync(0xFFFFFFFFu, src_j, b * 8);
            float wgt = __expf(e - m);
            s += wgt;
            const __half* row = g_xp + (size_t)src * HC + lane * VPL;
            if constexpr (VPL == 4) {
                uint2 raw = *reinterpret_cast<const uint2*>(row);
                float2 fa = __half22float2(*reinterpret_cast<__half2*>(&raw.x));
                float2 fb = __half22float2(*reinterpret_cast<__half2*>(&raw.y));
                acc[0] += wgt * fa.x; acc[1] += wgt * fa.y;
                acc[2] += wgt * fb.x; acc[3] += wgt * fb.y;
            } else {
                float2 fa = __half22float2(*reinterpret_cast<const __half2*>(row));
                acc[0] += wgt * fa.x; acc[1] += wgt * fa.y;
            }
        }
    }

    float inv = 1.f / (s + 1e-16f);
#pragma unroll
    for (int v = 0; v < VPL; v++) {
        float o = acc[v] * inv + bias[lane * VPL + v];
        if (DO_ELU) o = (o > 0.f) ? o : expm1f(o);
        g_h[(size_t)d * HC + lane * VPL + v] = o;
    }
}

// ---------------------------------------------------------------------------
// Layer 3 GEMM: xp3[N,10] = h[N,64] @ W3[64,10] (stride 16) + attn logits
// + global asrc max (slot 16).
// ---------------------------------------------------------------------------
__global__ void gemm3_kernel(const float* __restrict__ W3,
                             const float* __restrict__ a_s, const float* __restrict__ a_d,
                             int N) {
    __shared__ float Ws[64 * 10];
    __shared__ float as_s[10], ad_s[10];
    __shared__ unsigned s3;
    int t = threadIdx.x;
    for (int i = t; i < 640; i += blockDim.x) Ws[i] = W3[i];
    if (t < 10) { as_s[t] = a_s[t]; ad_s[t] = a_d[t]; }
    if (t == 0) s3 = 0u;
    __syncthreads();

    int r = (blockIdx.x * blockDim.x + t) >> 5;
    int lane = t & 31;
    if (r < N) {
        float h0 = g_h[(size_t)r * 64 + lane];
        float h1 = g_h[(size_t)r * 64 + 32 + lane];
        float p[10];
#pragma unroll
        for (int c = 0; c < 10; c++)
            p[c] = h0 * Ws[lane * 10 + c] + h1 * Ws[(lane + 32) * 10 + c];
#pragma unroll
        for (int c = 0; c < 10; c++) {
#pragma unroll
            for (int off = 16; off >= 1; off >>= 1)
                p[c] += __shfl_xor_sync(0xFFFFFFFFu, p[c], off);
        }
        if (lane == 0) {
            float ss = 0.f, sd = 0.f;
#pragma unroll
            for (int c = 0; c < 10; c++) {
                g_xp3[(size_t)r * 16 + c] = p[c];
                ss += p[c] * as_s[c];
                sd += p[c] * ad_s[c];
            }
            g_asrc[r] = ss;
            g_adst[r] = sd;
            atomicMax(&s3, encf(ss));
        }
    }
    __syncthreads();
    if (t == 0) atomicMax(&g_gmax[16], s3);
}

// ---------------------------------------------------------------------------
// Layer 3 aggregation + log_softmax. One thread per destination, single-pass.
// ---------------------------------------------------------------------------
__global__ void aggregate3_kernel(const float* __restrict__ bias,
                                  float* __restrict__ out, int N) {
    int d = blockIdx.x * blockDim.x + threadIdx.x;
    if (d >= N) return;
    float adst_d = g_adst[d];
    int lo = g_row[d], hi = g_row[d + 1];

    float em = decf(g_gmax[16]) + adst_d;
    float m = (em > 0.f) ? em : 0.2f * em;

    float s = 0.f;
    float acc[10];
#pragma unroll
    for (int c = 0; c < 10; c++) acc[c] = 0.f;

    for (int i = lo; i < hi; i++) {
        int src = g_csr[i];
        float e = g_asrc[src] + adst_d;
        e = (e > 0.f) ? e : 0.2f * e;
        float wgt = __expf(e - m);
        s += wgt;
        const float* row = g_xp3 + (size_t)src * 16;
        float4 v0 = *reinterpret_cast<const float4*>(row);
        float4 v1 = *reinterpret_cast<const float4*>(row + 4);
        float2 v2 = *reinterpret_cast<const float2*>(row + 8);
        acc[0] += wgt * v0.x; acc[1] += wgt * v0.y; acc[2] += wgt * v0.z; acc[3] += wgt * v0.w;
        acc[4] += wgt * v1.x; acc[5] += wgt * v1.y; acc[6] += wgt * v1.z; acc[7] += wgt * v1.w;
        acc[8] += wgt * v2.x; acc[9] += wgt * v2.y;
    }
    float inv = 1.f / (s + 1e-16f);
    float logit[10];
    float mx = -INFINITY;
#pragma unroll
    for (int c = 0; c < 10; c++) {
        logit[c] = acc[c] * inv + bias[c];
        mx = fmaxf(mx, logit[c]);
    }
    float se = 0.f;
#pragma unroll
    for (int c = 0; c < 10; c++) se += __expf(logit[c] - mx);
    float lse = logf(se) + mx;
#pragma unroll
    for (int c = 0; c < 10; c++) out[(size_t)d * 10 + c] = logit[c] - lse;
}

// ---------------------------------------------------------------------------
// Launcher. CSR build on side stream overlapping GEMM1 (4th-created: ncu).
// ---------------------------------------------------------------------------
extern "C" void kernel_launch(void* const* d_in, const int* in_sizes, int n_in,
                              void* d_out, int out_size) {
    const float* x   = (const float*)d_in[0];
    const void*  ei  = d_in[1];
    const float* W1 = (const float*)d_in[2];
    const float* a1s = (const float*)d_in[3];
    const float* a1d = (const float*)d_in[4];
    const float* b1 = (const float*)d_in[5];
    const float* W2 = (const float*)d_in[6];
    const float* a2s = (const float*)d_in[7];
    const float* a2d = (const float*)d_in[8];
    const float* b2 = (const float*)d_in[9];
    const float* W3 = (const float*)d_in[10];
    const float* a3s = (const float*)d_in[11];
    const float* a3d = (const float*)d_in[12];
    const float* b3 = (const float*)d_in[13];
    float* out = (float*)d_out;

    int N = in_sizes[0] / 256;
    int E = in_sizes[1] / 2;
    int nb = (N + 255) / 256;

    static cudaStream_t s_side = nullptr;
    static cudaEvent_t ev_fork = nullptr, ev_join = nullptr;
    if (!s_side) {
        cudaStreamCreateWithFlags(&s_side, cudaStreamNonBlocking);
        cudaEventCreateWithFlags(&ev_fork, cudaEventDisableTiming);
        cudaEventCreateWithFlags(&ev_join, cudaEventDisableTiming);
    }

    constexpr int SMEM1 = (2 * 128 * 36 + 2 * 32 * (128 + 8) + 2 * 128) * 4;
    constexpr int SMEM2 = (2 * 128 * 36 + 2 * 32 * (64 + 8) + 2 * 64) * 4;
    cudaFuncSetAttribute((const void*)gemm_mma_kernel<256, 128, 8, 16, false, 0>,
                         cudaFuncAttributeMaxDynamicSharedMemorySize, SMEM1);
    cudaFuncSetAttribute((const void*)gemm_mma_kernel<128, 64, 8, 8, true, 8>,
                         cudaFuncAttributeMaxDynamicSharedMemorySize, SMEM2);

    int warp_blocks = (N + 7) / 8;
    int gemm_blocks = (N + 127) / 128;

    // Fork: CSR build on side stream, GEMM1 on main stream.
    cudaEventRecord(ev_fork, 0);
    cudaStreamWaitEvent(s_side, ev_fork, 0);

    convert_hist_kernel<<<(E + 255) / 256, 256, 0, s_side>>>(ei, E, N);       // 1
    scan_blocks_kernel<<<nb, 256, 0, s_side>>>(N);                            // 2
    scan_top_kernel<<<1, 1024, 0, s_side>>>(nb, N);                           // 3
    gemm_mma_kernel<256, 128, 8, 16, false, 0><<<gemm_blocks, 256, SMEM1>>>(  // 4 (main)
        x, W1, a1s, a1d, N);
    scan_add_seed_kernel<<<nb, 256, 0, s_side>>>(N);                          // 5
    scatter_kernel<<<(E + 255) / 256, 256, 0, s_side>>>(E);                   // 6
    cudaEventRecord(ev_join, s_side);
    cudaStreamWaitEvent(0, ev_join, 0);

    aggregate_kernel<8, 16, true, 0><<<warp_blocks, 256>>>(b1, N);            // 7

    gemm_mma_kernel<128, 64, 8, 8, true, 8><<<gemm_blocks, 256, SMEM2>>>(     // 8
        nullptr, W2, a2s, a2d, N);
    aggregate_kernel<8, 8, true, 8><<<warp_blocks, 256>>>(b2, N);             // 9

    gemm3_kernel<<<warp_blocks, 256>>>(W3, a3s, a3d, N);                      // 10
    aggregate3_kernel<<<(N + 255) / 256, 256>>>(b3, out, N);                  // 11
}

// round 15
// speedup vs baseline: 1.1243x; 1.1243x over previous
#include <cuda_runtime.h>
#include <cuda_fp16.h>
#include <math.h>
#include <stdint.h>

// ---------------------------------------------------------------------------
// N=100000 nodes, F=256, E=1600000.
// Layer 1: 256 -> 8 heads x 16   (HC=128)
// Layer 2: 128 -> 8 heads x 8    (HC=64)
// Layer 3:  64 -> 1 head  x 10   (HC=10), then log_softmax
// ---------------------------------------------------------------------------
#define MAXN 100000
#define MAXE 1600000

__device__ __align__(16) __half g_xp[MAXN * 128];  // transformed features (fp16)
__device__ __align__(16) float g_h [MAXN * 128];   // layer activations (fp32)
__device__ __align__(16) float g_xp3[MAXN * 16];   // layer-3 logits (fp32)
__device__ float g_asrc[MAXN * 8];
__device__ float g_adst[MAXN * 8];
__device__ int   g_srcbuf[MAXE];
__device__ int   g_dstbuf[MAXE];
__device__ int   g_deg[MAXN];          // BSS-zero at load; re-zeroed by scan
__device__ int   g_cursor[MAXN];
__device__ int   g_row[MAXN + 1];
__device__ int   g_csr[MAXE + MAXN];
__device__ int   g_bsum[1024];
__device__ int   g_boff[1024];
// Global per-head asrc maxima (ordered-uint encoded). Slots: M1=0-7, M2=8-15, M3=16.
__device__ unsigned g_gmax[17];

// ---------------------------------------------------------------------------
// PTX helpers
// ---------------------------------------------------------------------------
__device__ __forceinline__ void cp_async16(uint32_t dst, const void* src) {
    asm volatile("cp.async.cg.shared.global [%0], [%1], 16;" :: "r"(dst), "l"(src));
}
#define CP_COMMIT() asm volatile("cp.async.commit_group;")
#define CP_WAIT0()  asm volatile("cp.async.wait_group 0;")

__device__ __forceinline__ uint32_t f2tf(float f) {
    uint32_t r;
    asm("cvt.rna.tf32.f32 %0, %1;" : "=r"(r) : "f"(f));
    return r;
}

// Ordered-uint encoding: strictly monotone float -> unsigned.
__device__ __forceinline__ unsigned encf(float f) {
    unsigned b = __float_as_uint(f);
    return (b & 0x80000000u) ? ~b : (b | 0x80000000u);
}
__device__ __forceinline__ float decf(unsigned u) {
    return __uint_as_float((u & 0x80000000u) ? (u & 0x7FFFFFFFu) : ~u);
}

__device__ __forceinline__ void mma_tf32(float& d0, float& d1, float& d2, float& d3,
                                         uint32_t a0, uint32_t a1, uint32_t a2, uint32_t a3,
                                         uint32_t b0, uint32_t b1) {
    asm("mma.sync.aligned.m16n8k8.row.col.f32.tf32.tf32.f32 "
        "{%0,%1,%2,%3}, {%4,%5,%6,%7}, {%8,%9}, {%0,%1,%2,%3};"
        : "+f"(d0), "+f"(d1), "+f"(d2), "+f"(d3)
        : "r"(a0), "r"(a1), "r"(a2), "r"(a3), "r"(b0), "r"(b1));
}

// ---------------------------------------------------------------------------
// Edge conversion (dtype detect inlined) + degree histogram
// ---------------------------------------------------------------------------
__global__ void convert_hist_kernel(const void* ei, int E, int N) {
    __shared__ int s64;
    if (threadIdx.x == 0) {
        const long long* p = (const long long*)ei;
        int ok = 1;
        for (int i = 0; i < 8; i++) {
            long long v = p[i];
            if (v < 0 || v >= (long long)N) ok = 0;
        }
        s64 = ok;
    }
    __syncthreads();
    int e = blockIdx.x * blockDim.x + threadIdx.x;
    if (e >= E) return;
    int src, dst;
    if (s64) {
        const long long* p = (const long long*)ei;
        src = (int)p[e];
        dst = (int)p[(size_t)E + e];
    } else {
        const int* p = (const int*)ei;
        src = p[e];
        dst = p[(size_t)E + e];
    }
    g_srcbuf[e] = src;
    g_dstbuf[e] = dst;
    atomicAdd(&g_deg[dst], 1);
}

// ---------------------------------------------------------------------------
// Parallel exclusive scan (3 kernels) over (deg+1); seeds self loops + cursors.
// ---------------------------------------------------------------------------
__global__ void scan_blocks_kernel(int N) {
    int i = blockIdx.x * 256 + threadIdx.x;
    int v = 0;
    if (i < N) {
        v = g_deg[i] + 1;   // +1 = self loop
        g_deg[i] = 0;       // reset for next launch
    }
    int lane = threadIdx.x & 31, wid = threadIdx.x >> 5;
    int x = v;
#pragma unroll
    for (int off = 1; off < 32; off <<= 1) {
        int t = __shfl_up_sync(0xFFFFFFFFu, x, off);
        if (lane >= off) x += t;
    }
    __shared__ int wsum[8];
    if (lane == 31) wsum[wid] = x;
    __syncthreads();
    if (threadIdx.x == 0) {
        int run = 0;
#pragma unroll
        for (int w = 0; w < 8; w++) { int t = wsum[w]; wsum[w] = run; run += t; }
        g_bsum[blockIdx.x] = run;
    }
    __syncthreads();
    if (i < N) g_row[i] = x - v + wsum[wid];
}

__global__ void scan_top_kernel(int nb, int N) {
    int t = threadIdx.x;
    int v = (t < nb) ? g_bsum[t] : 0;
    int lane = t & 31, wid = t >> 5;
    int x = v;
#pragma unroll
    for (int off = 1; off < 32; off <<= 1) {
        int s = __shfl_up_sync(0xFFFFFFFFu, x, off);
        if (lane >= off) x += s;
    }
    __shared__ int wsum[32];
    if (lane == 31) wsum[wid] = x;
    __syncthreads();
    if (t == 0) {
        int run = 0;
#pragma unroll
        for (int w = 0; w < 32; w++) { int s = wsum[w]; wsum[w] = run; run += s; }
        g_row[N] = run;
    }
    __syncthreads();
    if (t < nb) g_boff[t] = x - v + wsum[wid];
}

__global__ void scan_add_seed_kernel(int N) {
    int i = blockIdx.x * 256 + threadIdx.x;
    if (i >= N) return;
    int r = g_row[i] + g_boff[i >> 8];
    g_row[i] = r;
    g_csr[r] = i;          // self loop in slot 0
    g_cursor[i] = r + 1;
}

__global__ void scatter_kernel(int E) {
    int e = blockIdx.x * blockDim.x + threadIdx.x;
    if (e < E) {
        int pos = atomicAdd(&g_cursor[g_dstbuf[e]], 1);
        g_csr[pos] = g_srcbuf[e];
    }
}

// ---------------------------------------------------------------------------
// Tensor-core GEMM (tf32 mma.sync) + fused attention logits + global asrc max.
// ---------------------------------------------------------------------------
template <int KIN, int KOUT, int H, int C, bool READ_H, int GOFF>
__global__ void gemm_mma_kernel(const float* __restrict__ Ain,
                                const float* __restrict__ W,
                                const float* __restrict__ a_s,
                                const float* __restrict__ a_d,
                                int N) {
    constexpr int BM = 128, BK = 32, BN = KOUT;
    constexpr int NT = 256;
    constexpr int SA = 36;
    constexpr int SB = BN + 8;
    constexpr int T  = KIN / BK;
    constexpr int BNW = BN / 2;
    constexpr int NTILES = BNW / 8;
    constexpr int MTILES = 2;
    constexpr int NHL = BNW / C;
    constexpr int AS_SZ = 2 * BM * SA;
    constexpr int BS_SZ = 2 * BK * SB;

    extern __shared__ float sm[];
    float* As  = sm;
    float* Bs  = sm + AS_SZ;
    float* s_as = sm + AS_SZ + BS_SZ;
    float* s_ad = s_as + BN;
    __shared__ unsigned s_enc[H];

    const float* A = READ_H ? g_h : Ain;
    int tid = threadIdx.x;
    int row0 = blockIdx.x * BM;

    for (int i = tid; i < BN; i += NT) { s_as[i] = a_s[i]; s_ad[i] = a_d[i]; }
    if (tid < H) s_enc[tid] = 0u;

    auto load_tile = [&](int t, int b) {
        int k0 = t * BK;
#pragma unroll
        for (int idx = tid; idx < BM * (BK / 4); idx += NT) {
            int m = idx >> 3, k4 = idx & 7;
            int gr = min(row0 + m, N - 1);
            cp_async16((uint32_t)__cvta_generic_to_shared(&As[b * BM * SA + m * SA + k4 * 4]),
                       &A[(size_t)gr * KIN + k0 + k4 * 4]);
        }
#pragma unroll
        for (int idx = tid; idx < BK * (BN / 4); idx += NT) {
            int k = idx / (BN / 4), n4 = idx % (BN / 4);
            cp_async16((uint32_t)__cvta_generic_to_shared(&Bs[b * BK * SB + k * SB + n4 * 4]),
                       &W[(size_t)(k0 + k) * KOUT + n4 * 4]);
        }
        CP_COMMIT();
    };

    int lane = tid & 31;
    int gid = lane >> 2, tig = lane & 3;
    int w = tid >> 5;
    int warp_n = w & 1, warp_m = w >> 1;
    int mbase = warp_m * 32;
    int nbase = warp_n * BNW;

    float acc[MTILES][NTILES][4];
#pragma unroll
    for (int mt = 0; mt < MTILES; mt++)
#pragma unroll
        for (int nt = 0; nt < NTILES; nt++)
#pragma unroll
            for (int q = 0; q < 4; q++) acc[mt][nt][q] = 0.f;

    load_tile(0, 0);
    CP_WAIT0();
    __syncthreads();

    for (int t = 0; t < T; t++) {
        if (t + 1 < T) load_tile(t + 1, (t + 1) & 1);
        int b = t & 1;
        const float* Ab = &As[b * BM * SA];
        const float* Bb = &Bs[b * BK * SB];
#pragma unroll
        for (int k8 = 0; k8 < BK / 8; k8++) {
            int kk = k8 * 8;
            uint32_t af[MTILES][4];
#pragma unroll
            for (int mt = 0; mt < MTILES; mt++) {
                const float* ar = &Ab[(mbase + mt * 16 + gid) * SA + kk + tig];
                af[mt][0] = f2tf(ar[0]);
                af[mt][1] = f2tf(ar[8 * SA]);
                af[mt][2] = f2tf(ar[4]);
                af[mt][3] = f2tf(ar[8 * SA + 4]);
            }
            uint32_t bf[NTILES][2];
#pragma unroll
            for (int nt = 0; nt < NTILES; nt++) {
                const float* br = &Bb[(kk + tig) * SB + nbase + nt * 8 + gid];
                bf[nt][0] = __float_as_uint(br[0]);
                bf[nt][1] = __float_as_uint(br[4 * SB]);
            }
#pragma unroll
            for (int mt = 0; mt < MTILES; mt++)
#pragma unroll
                for (int nt = 0; nt < NTILES; nt++)
                    mma_tf32(acc[mt][nt][0], acc[mt][nt][1], acc[mt][nt][2], acc[mt][nt][3],
                             af[mt][0], af[mt][1], af[mt][2], af[mt][3],
                             bf[nt][0], bf[nt][1]);
        }
        if (t + 1 < T) {
            CP_WAIT0();
            __syncthreads();
        }
    }

#pragma unroll
    for (int mt = 0; mt < MTILES; mt++) {
        int r0 = row0 + mbase + mt * 16 + gid;
        int r1 = r0 + 8;
        float ps0[NHL], pd0[NHL], ps1[NHL], pd1[NHL];
#pragma unroll
        for (int hl = 0; hl < NHL; hl++) { ps0[hl] = pd0[hl] = ps1[hl] = pd1[hl] = 0.f; }
#pragma unroll
        for (int nt = 0; nt < NTILES; nt++) {
            int col = nbase + nt * 8 + 2 * tig;
            int hl = (nt * 8) / C;
            float d0 = acc[mt][nt][0], d1 = acc[mt][nt][1];
            float d2 = acc[mt][nt][2], d3 = acc[mt][nt][3];
            if (r0 < N) *reinterpret_cast<__half2*>(&g_xp[(size_t)r0 * KOUT + col]) =
                __floats2half2_rn(d0, d1);
            if (r1 < N) *reinterpret_cast<__half2*>(&g_xp[(size_t)r1 * KOUT + col]) =
                __floats2half2_rn(d2, d3);
            float w0 = s_as[col], w1 = s_as[col + 1];
            float v0 = s_ad[col], v1 = s_ad[col + 1];
            ps0[hl] += d0 * w0 + d1 * w1;
            pd0[hl] += d0 * v0 + d1 * v1;
            ps1[hl] += d2 * w0 + d3 * w1;
            pd1[hl] += d2 * v0 + d3 * v1;
        }
#pragma unroll
        for (int hl = 0; hl < NHL; hl++) {
            ps0[hl] += __shfl_xor_sync(0xFFFFFFFFu, ps0[hl], 1);
            ps0[hl] += __shfl_xor_sync(0xFFFFFFFFu, ps0[hl], 2);
            pd0[hl] += __shfl_xor_sync(0xFFFFFFFFu, pd0[hl], 1);
            pd0[hl] += __shfl_xor_sync(0xFFFFFFFFu, pd0[hl], 2);
            ps1[hl] += __shfl_xor_sync(0xFFFFFFFFu, ps1[hl], 1);
            ps1[hl] += __shfl_xor_sync(0xFFFFFFFFu, ps1[hl], 2);
            pd1[hl] += __shfl_xor_sync(0xFFFFFFFFu, pd1[hl], 1);
            pd1[hl] += __shfl_xor_sync(0xFFFFFFFFu, pd1[hl], 2);
        }
        if (tig == 0) {
#pragma unroll
            for (int hl = 0; hl < NHL; hl++) {
                int head = nbase / C + hl;
                if (r0 < N) {
                    g_asrc[(size_t)r0 * H + head] = ps0[hl];
                    g_adst[(size_t)r0 * H + head] = pd0[hl];
                    atomicMax(&s_enc[head], encf(ps0[hl]));
                }
                if (r1 < N) {
                    g_asrc[(size_t)r1 * H + head] = ps1[hl];
                    g_adst[(size_t)r1 * H + head] = pd1[hl];
                    atomicMax(&s_enc[head], encf(ps1[hl]));
                }
            }
        }
    }
    __syncthreads();
    if (tid < H) atomicMax(&g_gmax[GOFF + tid], s_enc[tid]);
}

// ---------------------------------------------------------------------------
// Aggregation: warp-per-dst, single-pass (global-max bound), DUAL-STREAM edge
// walk (front+back halves simultaneously -> 2x independent load chains and
// 2x independent gathers per unrolled step). Fast ELU via __expf.
// ---------------------------------------------------------------------------
template <int H, int C, bool DO_ELU, int GOFF>
__global__ void aggregate_kernel(const float* __restrict__ bias, int N) {
    constexpr int HC = H * C;
    constexpr int VPL = HC / 32;
    constexpr int LPH = C / VPL;

    int d = (blockIdx.x * blockDim.x + threadIdx.x) >> 5;
    int lane = threadIdx.x & 31;
    if (d >= N) return;
    int head = lane / LPH;
    float adst_h = g_adst[(size_t)d * H + head];

    float M = decf(g_gmax[GOFF + head]);
    float em = M + adst_h;
    float m = (em > 0.f) ? em : 0.2f * em;   // >= all logits for this (dst, head)

    int lo = g_row[d], hi = g_row[d + 1];
    int len = hi - lo;
    int half = len >> 1;

    float s = 0.f;
    float acc[VPL];
#pragma unroll
    for (int v = 0; v < VPL; v++) acc[v] = 0.f;

    auto gather = [&](int src, float wgt) {
        const __half* row = g_xp + (size_t)src * HC + lane * VPL;
        if constexpr (VPL == 4) {
            uint2 raw = *reinterpret_cast<const uint2*>(row);
            float2 fa = __half22float2(*reinterpret_cast<__half2*>(&raw.x));
            float2 fb = __half22float2(*reinterpret_cast<__half2*>(&raw.y));
            acc[0] += wgt * fa.x; acc[1] += wgt * fa.y;
            acc[2] += wgt * fb.x; acc[3] += wgt * fb.y;
        } else {
            float2 fa = __half22float2(*reinterpret_cast<const __half2*>(row));
            acc[0] += wgt * fa.x; acc[1] += wgt * fa.y;
        }
    };

#pragma unroll 2
    for (int k = 0; k < half; k++) {
        int srcA = g_csr[lo + k];
        int srcB = g_csr[lo + half + k];
        float eA = g_asrc[(size_t)srcA * H + head] + adst_h;
        float eB = g_asrc[(size_t)srcB * H + head] + adst_h;
        eA = (eA > 0.f) ? eA : 0.2f * eA;
        eB = (eB > 0.f) ? eB : 0.2f * eB;
        float wA = __expf(eA - m);
        float wB = __expf(eB - m);
        s += wA + wB;
        gather(srcA, wA);
        gather(srcB, wB);
    }
    if (len & 1) {
        int src = g_csr[hi - 1];
        float e = g_asrc[(size_t)src * H + head] + adst_h;
        e = (e > 0.f) ? e : 0.2f * e;
        float wgt = __expf(e - m);
        s += wgt;
        gather(src, wgt);
    }

    float inv = 1.f / (s + 1e-16f);
#pragma unroll
    for (int v = 0; v < VPL; v++) {
        float o = acc[v] * inv + bias[lane * VPL + v];
        if (DO_ELU) o = (o > 0.f) ? o : (__expf(o) - 1.f);   // fast ELU
        g_h[(size_t)d * HC + lane * VPL + v] = o;
    }
}

// ---------------------------------------------------------------------------
// Layer 3 GEMM: xp3[N,10] = h[N,64] @ W3[64,10] (stride 16) + attn logits
// + global asrc max (slot 16).
// ---------------------------------------------------------------------------
__global__ void gemm3_kernel(const float* __restrict__ W3,
                             const float* __restrict__ a_s, const float* __restrict__ a_d,
                             int N) {
    __shared__ float Ws[64 * 10];
    __shared__ float as_s[10], ad_s[10];
    __shared__ unsigned s3;
    int t = threadIdx.x;
    for (int i = t; i < 640; i += blockDim.x) Ws[i] = W3[i];
    if (t < 10) { as_s[t] = a_s[t]; ad_s[t] = a_d[t]; }
    if (t == 0) s3 = 0u;
    __syncthreads();

    int r = (blockIdx.x * blockDim.x + t) >> 5;
    int lane = t & 31;
    if (r < N) {
        float h0 = g_h[(size_t)r * 64 + lane];
        float h1 = g_h[(size_t)r * 64 + 32 + lane];
        float p[10];
#pragma unroll
        for (int c = 0; c < 10; c++)
            p[c] = h0 * Ws[lane * 10 + c] + h1 * Ws[(lane + 32) * 10 + c];
#pragma unroll
        for (int c = 0; c < 10; c++) {
#pragma unroll
            for (int off = 16; off >= 1; off >>= 1)
                p[c] += __shfl_xor_sync(0xFFFFFFFFu, p[c], off);
        }
        if (lane == 0) {
            float ss = 0.f, sd = 0.f;
#pragma unroll
            for (int c = 0; c < 10; c++) {
                g_xp3[(size_t)r * 16 + c] = p[c];
                ss += p[c] * as_s[c];
                sd += p[c] * ad_s[c];
            }
            g_asrc[r] = ss;
            g_adst[r] = sd;
            atomicMax(&s3, encf(ss));
        }
    }
    __syncthreads();
    if (t == 0) atomicMax(&g_gmax[16], s3);
}

// ---------------------------------------------------------------------------
// Layer 3 aggregation + log_softmax. One thread per destination, single-pass.
// ---------------------------------------------------------------------------
__global__ void aggregate3_kernel(const float* __restrict__ bias,
                                  float* __restrict__ out, int N) {
    int d = blockIdx.x * blockDim.x + threadIdx.x;
    if (d >= N) return;
    float adst_d = g_adst[d];
    int lo = g_row[d], hi = g_row[d + 1];

    float em = decf(g_gmax[16]) + adst_d;
    float m = (em > 0.f) ? em : 0.2f * em;

    float s = 0.f;
    float acc[10];
#pragma unroll
    for (int c = 0; c < 10; c++) acc[c] = 0.f;

    for (int i = lo; i < hi; i++) {
        int src = g_csr[i];
        float e = g_asrc[src] + adst_d;
        e = (e > 0.f) ? e : 0.2f * e;
        float wgt = __expf(e - m);
        s += wgt;
        const float* row = g_xp3 + (size_t)src * 16;
        float4 v0 = *reinterpret_cast<const float4*>(row);
        float4 v1 = *reinterpret_cast<const float4*>(row + 4);
        float2 v2 = *reinterpret_cast<const float2*>(row + 8);
        acc[0] += wgt * v0.x; acc[1] += wgt * v0.y; acc[2] += wgt * v0.z; acc[3] += wgt * v0.w;
        acc[4] += wgt * v1.x; acc[5] += wgt * v1.y; acc[6] += wgt * v1.z; acc[7] += wgt * v1.w;
        acc[8] += wgt * v2.x; acc[9] += wgt * v2.y;
    }
    float inv = 1.f / (s + 1e-16f);
    float logit[10];
    float mx = -INFINITY;
#pragma unroll
    for (int c = 0; c < 10; c++) {
        logit[c] = acc[c] * inv + bias[c];
        mx = fmaxf(mx, logit[c]);
    }
    float se = 0.f;
#pragma unroll
    for (int c = 0; c < 10; c++) se += __expf(logit[c] - mx);
    float lse = logf(se) + mx;
#pragma unroll
    for (int c = 0; c < 10; c++) out[(size_t)d * 10 + c] = logit[c] - lse;
}

// ---------------------------------------------------------------------------
// Launcher. CSR build on side stream overlapping GEMM1 (4th-created: ncu).
// ---------------------------------------------------------------------------
extern "C" void kernel_launch(void* const* d_in, const int* in_sizes, int n_in,
                              void* d_out, int out_size) {
    const float* x   = (const float*)d_in[0];
    const void*  ei  = d_in[1];
    const float* W1 = (const float*)d_in[2];
    const float* a1s = (const float*)d_in[3];
    const float* a1d = (const float*)d_in[4];
    const float* b1 = (const float*)d_in[5];
    const float* W2 = (const float*)d_in[6];
    const float* a2s = (const float*)d_in[7];
    const float* a2d = (const float*)d_in[8];
    const float* b2 = (const float*)d_in[9];
    const float* W3 = (const float*)d_in[10];
    const float* a3s = (const float*)d_in[11];
    const float* a3d = (const float*)d_in[12];
    const float* b3 = (const float*)d_in[13];
    float* out = (float*)d_out;

    int N = in_sizes[0] / 256;
    int E = in_sizes[1] / 2;
    int nb = (N + 255) / 256;

    static cudaStream_t s_side = nullptr;
    static cudaEvent_t ev_fork = nullptr, ev_join = nullptr;
    if (!s_side) {
        cudaStreamCreateWithFlags(&s_side, cudaStreamNonBlocking);
        cudaEventCreateWithFlags(&ev_fork, cudaEventDisableTiming);
        cudaEventCreateWithFlags(&ev_join, cudaEventDisableTiming);
    }

    constexpr int SMEM1 = (2 * 128 * 36 + 2 * 32 * (128 + 8) + 2 * 128) * 4;
    constexpr int SMEM2 = (2 * 128 * 36 + 2 * 32 * (64 + 8) + 2 * 64) * 4;
    cudaFuncSetAttribute((const void*)gemm_mma_kernel<256, 128, 8, 16, false, 0>,
                         cudaFuncAttributeMaxDynamicSharedMemorySize, SMEM1);
    cudaFuncSetAttribute((const void*)gemm_mma_kernel<128, 64, 8, 8, true, 8>,
                         cudaFuncAttributeMaxDynamicSharedMemorySize, SMEM2);

    int warp_blocks = (N + 7) / 8;
    int gemm_blocks = (N + 127) / 128;

    // Fork: CSR build on side stream, GEMM1 on main stream.
    cudaEventRecord(ev_fork, 0);
    cudaStreamWaitEvent(s_side, ev_fork, 0);

    convert_hist_kernel<<<(E + 255) / 256, 256, 0, s_side>>>(ei, E, N);       // 1
    scan_blocks_kernel<<<nb, 256, 0, s_side>>>(N);                            // 2
    scan_top_kernel<<<1, 1024, 0, s_side>>>(nb, N);                           // 3
    gemm_mma_kernel<256, 128, 8, 16, false, 0><<<gemm_blocks, 256, SMEM1>>>(  // 4 (main)
        x, W1, a1s, a1d, N);
    scan_add_seed_kernel<<<nb, 256, 0, s_side>>>(N);                          // 5
    scatter_kernel<<<(E + 255) / 256, 256, 0, s_side>>>(E);                   // 6
    cudaEventRecord(ev_join, s_side);
    cudaStreamWaitEvent(0, ev_join, 0);

    aggregate_kernel<8, 16, true, 0><<<warp_blocks, 256>>>(b1, N);            // 7

    gemm_mma_kernel<128, 64, 8, 8, true, 8><<<gemm_blocks, 256, SMEM2>>>(     // 8
        nullptr, W2, a2s, a2d, N);
    aggregate_kernel<8, 8, true, 8><<<warp_blocks, 256>>>(b2, N);             // 9

    gemm3_kernel<<<warp_blocks, 256>>>(W3, a3s, a3d, N);                      // 10
    aggregate3_kernel<<<(N + 255) / 256, 256>>>(b3, out, N);                  // 11
}

// round 17
// speedup vs baseline: 1.1656x; 1.0367x over previous
#include <cuda_runtime.h>
#include <cuda_fp16.h>
#include <math.h>
#include <stdint.h>

// ---------------------------------------------------------------------------
// N=100000 nodes, F=256, E=1600000.
// Layer 1: 256 -> 8 heads x 16   (HC=128)
// Layer 2: 128 -> 8 heads x 8    (HC=64)  [layer-3 GEMM fused into its epilogue]
// Layer 3:  64 -> 1 head  x 10   (HC=10), then log_softmax
// ---------------------------------------------------------------------------
#define MAXN 100000
#define MAXE 1600000

__device__ __align__(16) __half g_xp[MAXN * 128];  // transformed features (fp16)
__device__ __align__(16) float g_h [MAXN * 128];   // layer-1 activations (fp32)
__device__ __align__(16) float g_xp3[MAXN * 16];   // layer-3 logits (fp32)
__device__ float g_asrc[MAXN * 8];
__device__ float g_adst[MAXN * 8];
__device__ float g_asrc3[MAXN];        // layer-3 attn logits (separate: no aliasing)
__device__ float g_adst3[MAXN];
__device__ int   g_srcbuf[MAXE];
__device__ int   g_dstbuf[MAXE];
__device__ int   g_deg[MAXN];          // BSS-zero at load; re-zeroed by scan
__device__ int   g_cursor[MAXN];
__device__ int   g_row[MAXN + 1];
__device__ int   g_csr[MAXE + MAXN];
__device__ int   g_bsum[1024];
__device__ int   g_boff[1024];
// Global per-head asrc maxima (ordered-uint encoded). Slots: M1=0-7, M2=8-15, M3=16.
__device__ unsigned g_gmax[17];

// ---------------------------------------------------------------------------
// PTX helpers
// ---------------------------------------------------------------------------
__device__ __forceinline__ void cp_async16(uint32_t dst, const void* src) {
    asm volatile("cp.async.cg.shared.global [%0], [%1], 16;" :: "r"(dst), "l"(src));
}
#define CP_COMMIT() asm volatile("cp.async.commit_group;")
#define CP_WAIT0()  asm volatile("cp.async.wait_group 0;")

__device__ __forceinline__ uint32_t f2tf(float f) {
    uint32_t r;
    asm("cvt.rna.tf32.f32 %0, %1;" : "=r"(r) : "f"(f));
    return r;
}

// Ordered-uint encoding: strictly monotone float -> unsigned.
__device__ __forceinline__ unsigned encf(float f) {
    unsigned b = __float_as_uint(f);
    return (b & 0x80000000u) ? ~b : (b | 0x80000000u);
}
__device__ __forceinline__ float decf(unsigned u) {
    return __uint_as_float((u & 0x80000000u) ? (u & 0x7FFFFFFFu) : ~u);
}

__device__ __forceinline__ void mma_tf32(float& d0, float& d1, float& d2, float& d3,
                                         uint32_t a0, uint32_t a1, uint32_t a2, uint32_t a3,
                                         uint32_t b0, uint32_t b1) {
    asm("mma.sync.aligned.m16n8k8.row.col.f32.tf32.tf32.f32 "
        "{%0,%1,%2,%3}, {%4,%5,%6,%7}, {%8,%9}, {%0,%1,%2,%3};"
        : "+f"(d0), "+f"(d1), "+f"(d2), "+f"(d3)
        : "r"(a0), "r"(a1), "r"(a2), "r"(a3), "r"(b0), "r"(b1));
}

// ---------------------------------------------------------------------------
// Edge conversion (dtype detect inlined) + degree histogram
// ---------------------------------------------------------------------------
__global__ void convert_hist_kernel(const void* ei, int E, int N) {
    __shared__ int s64;
    if (threadIdx.x == 0) {
        const long long* p = (const long long*)ei;
        int ok = 1;
        for (int i = 0; i < 8; i++) {
            long long v = p[i];
            if (v < 0 || v >= (long long)N) ok = 0;
        }
        s64 = ok;
    }
    __syncthreads();
    int e = blockIdx.x * blockDim.x + threadIdx.x;
    if (e >= E) return;
    int src, dst;
    if (s64) {
        const long long* p = (const long long*)ei;
        src = (int)p[e];
        dst = (int)p[(size_t)E + e];
    } else {
        const int* p = (const int*)ei;
        src = p[e];
        dst = p[(size_t)E + e];
    }
    g_srcbuf[e] = src;
    g_dstbuf[e] = dst;
    atomicAdd(&g_deg[dst], 1);
}

// ---------------------------------------------------------------------------
// Parallel exclusive scan (3 kernels) over (deg+1); seeds self loops + cursors.
// ---------------------------------------------------------------------------
__global__ void scan_blocks_kernel(int N) {
    int i = blockIdx.x * 256 + threadIdx.x;
    int v = 0;
    if (i < N) {
        v = g_deg[i] + 1;   // +1 = self loop
        g_deg[i] = 0;       // reset for next launch
    }
    int lane = threadIdx.x & 31, wid = threadIdx.x >> 5;
    int x = v;
#pragma unroll
    for (int off = 1; off < 32; off <<= 1) {
        int t = __shfl_up_sync(0xFFFFFFFFu, x, off);
        if (lane >= off) x += t;
    }
    __shared__ int wsum[8];
    if (lane == 31) wsum[wid] = x;
    __syncthreads();
    if (threadIdx.x == 0) {
        int run = 0;
#pragma unroll
        for (int w = 0; w < 8; w++) { int t = wsum[w]; wsum[w] = run; run += t; }
        g_bsum[blockIdx.x] = run;
    }
    __syncthreads();
    if (i < N) g_row[i] = x - v + wsum[wid];
}

__global__ void scan_top_kernel(int nb, int N) {
    int t = threadIdx.x;
    int v = (t < nb) ? g_bsum[t] : 0;
    int lane = t & 31, wid = t >> 5;
    int x = v;
#pragma unroll
    for (int off = 1; off < 32; off <<= 1) {
        int s = __shfl_up_sync(0xFFFFFFFFu, x, off);
        if (lane >= off) x += s;
    }
    __shared__ int wsum[32];
    if (lane == 31) wsum[wid] = x;
    __syncthreads();
    if (t == 0) {
        int run = 0;
#pragma unroll
        for (int w = 0; w < 32; w++) { int s = wsum[w]; wsum[w] = run; run += s; }
        g_row[N] = run;
    }
    __syncthreads();
    if (t < nb) g_boff[t] = x - v + wsum[wid];
}

__global__ void scan_add_seed_kernel(int N) {
    int i = blockIdx.x * 256 + threadIdx.x;
    if (i >= N) return;
    int r = g_row[i] + g_boff[i >> 8];
    g_row[i] = r;
    g_csr[r] = i;          // self loop in slot 0
    g_cursor[i] = r + 1;
}

__global__ void scatter_kernel(int E) {
    int e = blockIdx.x * blockDim.x + threadIdx.x;
    if (e < E) {
        int pos = atomicAdd(&g_cursor[g_dstbuf[e]], 1);
        g_csr[pos] = g_srcbuf[e];
    }
}

// ---------------------------------------------------------------------------
// Tensor-core GEMM (tf32 mma.sync) + fused attention logits + global asrc max.
// ---------------------------------------------------------------------------
template <int KIN, int KOUT, int H, int C, bool READ_H, int GOFF>
__global__ void gemm_mma_kernel(const float* __restrict__ Ain,
                                const float* __restrict__ W,
                                const float* __restrict__ a_s,
                                const float* __restrict__ a_d,
                                int N) {
    constexpr int BM = 128, BK = 32, BN = KOUT;
    constexpr int NT = 256;
    constexpr int SA = 36;
    constexpr int SB = BN + 8;
    constexpr int T  = KIN / BK;
    constexpr int BNW = BN / 2;
    constexpr int NTILES = BNW / 8;
    constexpr int MTILES = 2;
    constexpr int NHL = BNW / C;
    constexpr int AS_SZ = 2 * BM * SA;
    constexpr int BS_SZ = 2 * BK * SB;

    extern __shared__ float sm[];
    float* As  = sm;
    float* Bs  = sm + AS_SZ;
    float* s_as = sm + AS_SZ + BS_SZ;
    float* s_ad = s_as + BN;
    __shared__ unsigned s_enc[H];

    const float* A = READ_H ? g_h : Ain;
    int tid = threadIdx.x;
    int row0 = blockIdx.x * BM;

    for (int i = tid; i < BN; i += NT) { s_as[i] = a_s[i]; s_ad[i] = a_d[i]; }
    if (tid < H) s_enc[tid] = 0u;

    auto load_tile = [&](int t, int b) {
        int k0 = t * BK;
#pragma unroll
        for (int idx = tid; idx < BM * (BK / 4); idx += NT) {
            int m = idx >> 3, k4 = idx & 7;
            int gr = min(row0 + m, N - 1);
            cp_async16((uint32_t)__cvta_generic_to_shared(&As[b * BM * SA + m * SA + k4 * 4]),
                       &A[(size_t)gr * KIN + k0 + k4 * 4]);
        }
#pragma unroll
        for (int idx = tid; idx < BK * (BN / 4); idx += NT) {
            int k = idx / (BN / 4), n4 = idx % (BN / 4);
            cp_async16((uint32_t)__cvta_generic_to_shared(&Bs[b * BK * SB + k * SB + n4 * 4]),
                       &W[(size_t)(k0 + k) * KOUT + n4 * 4]);
        }
        CP_COMMIT();
    };

    int lane = tid & 31;
    int gid = lane >> 2, tig = lane & 3;
    int w = tid >> 5;
    int warp_n = w & 1, warp_m = w >> 1;
    int mbase = warp_m * 32;
    int nbase = warp_n * BNW;

    float acc[MTILES][NTILES][4];
#pragma unroll
    for (int mt = 0; mt < MTILES; mt++)
#pragma unroll
        for (int nt = 0; nt < NTILES; nt++)
#pragma unroll
            for (int q = 0; q < 4; q++) acc[mt][nt][q] = 0.f;

    load_tile(0, 0);
    CP_WAIT0();
    __syncthreads();

    for (int t = 0; t < T; t++) {
        if (t + 1 < T) load_tile(t + 1, (t + 1) & 1);
        int b = t & 1;
        const float* Ab = &As[b * BM * SA];
        const float* Bb = &Bs[b * BK * SB];
#pragma unroll
        for (int k8 = 0; k8 < BK / 8; k8++) {
            int kk = k8 * 8;
            uint32_t af[MTILES][4];
#pragma unroll
            for (int mt = 0; mt < MTILES; mt++) {
                const float* ar = &Ab[(mbase + mt * 16 + gid) * SA + kk + tig];
                af[mt][0] = f2tf(ar[0]);
                af[mt][1] = f2tf(ar[8 * SA]);
                af[mt][2] = f2tf(ar[4]);
                af[mt][3] = f2tf(ar[8 * SA + 4]);
            }
            uint32_t bf[NTILES][2];
#pragma unroll
            for (int nt = 0; nt < NTILES; nt++) {
                const float* br = &Bb[(kk + tig) * SB + nbase + nt * 8 + gid];
                bf[nt][0] = __float_as_uint(br[0]);
                bf[nt][1] = __float_as_uint(br[4 * SB]);
            }
#pragma unroll
            for (int mt = 0; mt < MTILES; mt++)
#pragma unroll
                for (int nt = 0; nt < NTILES; nt++)
                    mma_tf32(acc[mt][nt][0], acc[mt][nt][1], acc[mt][nt][2], acc[mt][nt][3],
                             af[mt][0], af[mt][1], af[mt][2], af[mt][3],
                             bf[nt][0], bf[nt][1]);
        }
        if (t + 1 < T) {
            CP_WAIT0();
            __syncthreads();
        }
    }

#pragma unroll
    for (int mt = 0; mt < MTILES; mt++) {
        int r0 = row0 + mbase + mt * 16 + gid;
        int r1 = r0 + 8;
        float ps0[NHL], pd0[NHL], ps1[NHL], pd1[NHL];
#pragma unroll
        for (int hl = 0; hl < NHL; hl++) { ps0[hl] = pd0[hl] = ps1[hl] = pd1[hl] = 0.f; }
#pragma unroll
        for (int nt = 0; nt < NTILES; nt++) {
            int col = nbase + nt * 8 + 2 * tig;
            int hl = (nt * 8) / C;
            float d0 = acc[mt][nt][0], d1 = acc[mt][nt][1];
            float d2 = acc[mt][nt][2], d3 = acc[mt][nt][3];
            if (r0 < N) *reinterpret_cast<__half2*>(&g_xp[(size_t)r0 * KOUT + col]) =
                __floats2half2_rn(d0, d1);
            if (r1 < N) *reinterpret_cast<__half2*>(&g_xp[(size_t)r1 * KOUT + col]) =
                __floats2half2_rn(d2, d3);
            float w0 = s_as[col], w1 = s_as[col + 1];
            float v0 = s_ad[col], v1 = s_ad[col + 1];
            ps0[hl] += d0 * w0 + d1 * w1;
            pd0[hl] += d0 * v0 + d1 * v1;
            ps1[hl] += d2 * w0 + d3 * w1;
            pd1[hl] += d2 * v0 + d3 * v1;
        }
#pragma unroll
        for (int hl = 0; hl < NHL; hl++) {
            ps0[hl] += __shfl_xor_sync(0xFFFFFFFFu, ps0[hl], 1);
            ps0[hl] += __shfl_xor_sync(0xFFFFFFFFu, ps0[hl], 2);
            pd0[hl] += __shfl_xor_sync(0xFFFFFFFFu, pd0[hl], 1);
            pd0[hl] += __shfl_xor_sync(0xFFFFFFFFu, pd0[hl], 2);
            ps1[hl] += __shfl_xor_sync(0xFFFFFFFFu, ps1[hl], 1);
            ps1[hl] += __shfl_xor_sync(0xFFFFFFFFu, ps1[hl], 2);
            pd1[hl] += __shfl_xor_sync(0xFFFFFFFFu, pd1[hl], 1);
            pd1[hl] += __shfl_xor_sync(0xFFFFFFFFu, pd1[hl], 2);
        }
        if (tig == 0) {
#pragma unroll
            for (int hl = 0; hl < NHL; hl++) {
                int head = nbase / C + hl;
                if (r0 < N) {
                    g_asrc[(size_t)r0 * H + head] = ps0[hl];
                    g_adst[(size_t)r0 * H + head] = pd0[hl];
                    atomicMax(&s_enc[head], encf(ps0[hl]));
                }
                if (r1 < N) {
                    g_asrc[(size_t)r1 * H + head] = ps1[hl];
                    g_adst[(size_t)r1 * H + head] = pd1[hl];
                    atomicMax(&s_enc[head], encf(ps1[hl]));
                }
            }
        }
    }
    __syncthreads();
    if (tid < H) atomicMax(&g_gmax[GOFF + tid], s_enc[tid]);
}

// ---------------------------------------------------------------------------
// Aggregation layer 1: warp-per-dst, single-pass (global-max bound),
// dual-stream edge walk, fast ELU. Writes g_h (fp32, HC=128).
// ---------------------------------------------------------------------------
__global__ void aggregate1_kernel(const float* __restrict__ bias, int N) {
    constexpr int H = 8, C = 16, HC = 128, VPL = 4, LPH = 4;

    int d = (blockIdx.x * blockDim.x + threadIdx.x) >> 5;
    int lane = threadIdx.x & 31;
    if (d >= N) return;
    int head = lane / LPH;
    float adst_h = g_adst[(size_t)d * H + head];

    float M = decf(g_gmax[0 + head]);
    float em = M + adst_h;
    float m = (em > 0.f) ? em : 0.2f * em;

    int lo = g_row[d], hi = g_row[d + 1];
    int len = hi - lo;
    int half = len >> 1;

    float s = 0.f;
    float acc[VPL] = {0.f, 0.f, 0.f, 0.f};

    auto gather = [&](int src, float wgt) {
        const __half* row = g_xp + (size_t)src * HC + lane * VPL;
        uint2 raw = *reinterpret_cast<const uint2*>(row);
        float2 fa = __half22float2(*reinterpret_cast<__half2*>(&raw.x));
        float2 fb = __half22float2(*reinterpret_cast<__half2*>(&raw.y));
        acc[0] += wgt * fa.x; acc[1] += wgt * fa.y;
        acc[2] += wgt * fb.x; acc[3] += wgt * fb.y;
    };

#pragma unroll 2
    for (int k = 0; k < half; k++) {
        int srcA = g_csr[lo + k];
        int srcB = g_csr[lo + half + k];
        float eA = g_asrc[(size_t)srcA * H + head] + adst_h;
        float eB = g_asrc[(size_t)srcB * H + head] + adst_h;
        eA = (eA > 0.f) ? eA : 0.2f * eA;
        eB = (eB > 0.f) ? eB : 0.2f * eB;
        float wA = __expf(eA - m);
        float wB = __expf(eB - m);
        s += wA + wB;
        gather(srcA, wA);
        gather(srcB, wB);
    }
    if (len & 1) {
        int src = g_csr[hi - 1];
        float e = g_asrc[(size_t)src * H + head] + adst_h;
        e = (e > 0.f) ? e : 0.2f * e;
        float wgt = __expf(e - m);
        s += wgt;
        gather(src, wgt);
    }

    float inv = 1.f / (s + 1e-16f);
#pragma unroll
    for (int v = 0; v < VPL; v++) {
        float o = acc[v] * inv + bias[lane * VPL + v];
        o = (o > 0.f) ? o : (__expf(o) - 1.f);
        g_h[(size_t)d * HC + lane * VPL + v] = o;
    }
}

// ---------------------------------------------------------------------------
// Aggregation layer 2 + FUSED layer-3 GEMM: warp-per-dst, single-pass.
// After computing h[64] (lane l holds h[2l], h[2l+1]), the warp directly
// computes xp3 = h @ W3 (64x10) + attn logits via butterfly reduction.
// Layer-3 logits go to SEPARATE buffers g_asrc3/g_adst3 (no aliasing with
// the layer-2 logits still being read by other warps).
// ---------------------------------------------------------------------------
__global__ void aggregate2_fused_kernel(const float* __restrict__ bias,
                                        const float* __restrict__ W3,
                                        const float* __restrict__ a3s,
                                        const float* __restrict__ a3d,
                                        int N) {
    constexpr int H = 8, C = 8, HC = 64, VPL = 2, LPH = 4;

    __shared__ float Ws[64 * 10];
    __shared__ float s_as3[10], s_ad3[10];
    __shared__ unsigned s_enc3;
    {
        int t = threadIdx.x;
        for (int i = t; i < 640; i += blockDim.x) Ws[i] = W3[i];
        if (t < 10) { s_as3[t] = a3s[t]; s_ad3[t] = a3d[t]; }
        if (t == 0) s_enc3 = 0u;
    }
    __syncthreads();

    int d = (blockIdx.x * blockDim.x + threadIdx.x) >> 5;
    int lane = threadIdx.x & 31;
    unsigned myenc = 0u;

    if (d < N) {
        int head = lane / LPH;
        float adst_h = g_adst[(size_t)d * H + head];

        float M = decf(g_gmax[8 + head]);
        float em = M + adst_h;
        float m = (em > 0.f) ? em : 0.2f * em;

        int lo = g_row[d], hi = g_row[d + 1];
        int len = hi - lo;
        int half = len >> 1;

        float s = 0.f;
        float acc[VPL] = {0.f, 0.f};

        auto gather = [&](int src, float wgt) {
            const __half* row = g_xp + (size_t)src * HC + lane * VPL;
            float2 fa = __half22float2(*reinterpret_cast<const __half2*>(row));
            acc[0] += wgt * fa.x; acc[1] += wgt * fa.y;
        };

#pragma unroll 2
        for (int k = 0; k < half; k++) {
            int srcA = g_csr[lo + k];
            int srcB = g_csr[lo + half + k];
            float eA = g_asrc[(size_t)srcA * H + head] + adst_h;
            float eB = g_asrc[(size_t)srcB * H + head] + adst_h;
            eA = (eA > 0.f) ? eA : 0.2f * eA;
            eB = (eB > 0.f) ? eB : 0.2f * eB;
            float wA = __expf(eA - m);
            float wB = __expf(eB - m);
            s += wA + wB;
            gather(srcA, wA);
            gather(srcB, wB);
        }
        if (len & 1) {
            int src = g_csr[hi - 1];
            float e = g_asrc[(size_t)src * H + head] + adst_h;
            e = (e > 0.f) ? e : 0.2f * e;
            float wgt = __expf(e - m);
            s += wgt;
            gather(src, wgt);
        }

        float inv = 1.f / (s + 1e-16f);
        float o0 = acc[0] * inv + bias[lane * VPL + 0];
        float o1 = acc[1] * inv + bias[lane * VPL + 1];
        o0 = (o0 > 0.f) ? o0 : (__expf(o0) - 1.f);
        o1 = (o1 > 0.f) ? o1 : (__expf(o1) - 1.f);

        // Fused layer-3 GEMM: p[c] = sum_l h[2l]*W3[2l][c] + h[2l+1]*W3[2l+1][c]
        const float* w0 = &Ws[(2 * lane) * 10];
        const float* w1 = &Ws[(2 * lane + 1) * 10];
        float p[10];
#pragma unroll
        for (int c = 0; c < 10; c++)
            p[c] = o0 * w0[c] + o1 * w1[c];
#pragma unroll
        for (int off = 16; off >= 1; off >>= 1) {
#pragma unroll
            for (int c = 0; c < 10; c++)
                p[c] += __shfl_xor_sync(0xFFFFFFFFu, p[c], off);
        }
        if (lane == 0) {
            float ss = 0.f, sd = 0.f;
#pragma unroll
            for (int c = 0; c < 10; c++) {
                g_xp3[(size_t)d * 16 + c] = p[c];
                ss += p[c] * s_as3[c];
                sd += p[c] * s_ad3[c];
            }
            g_asrc3[d] = ss;
            g_adst3[d] = sd;
            myenc = encf(ss);
        }
    }
    if (lane == 0) atomicMax(&s_enc3, myenc);
    __syncthreads();
    if (threadIdx.x == 0) atomicMax(&g_gmax[16], s_enc3);
}

// ---------------------------------------------------------------------------
// Layer 3 aggregation + log_softmax. One thread per destination, single-pass.
// ---------------------------------------------------------------------------
__global__ void aggregate3_kernel(const float* __restrict__ bias,
                                  float* __restrict__ out, int N) {
    int d = blockIdx.x * blockDim.x + threadIdx.x;
    if (d >= N) return;
    float adst_d = g_adst3[d];
    int lo = g_row[d], hi = g_row[d + 1];

    float em = decf(g_gmax[16]) + adst_d;
    float m = (em > 0.f) ? em : 0.2f * em;

    float s = 0.f;
    float acc[10];
#pragma unroll
    for (int c = 0; c < 10; c++) acc[c] = 0.f;

    for (int i = lo; i < hi; i++) {
        int src = g_csr[i];
        float e = g_asrc3[src] + adst_d;
        e = (e > 0.f) ? e : 0.2f * e;
        float wgt = __expf(e - m);
        s += wgt;
        const float* row = g_xp3 + (size_t)src * 16;
        float4 v0 = *reinterpret_cast<const float4*>(row);
        float4 v1 = *reinterpret_cast<const float4*>(row + 4);
        float2 v2 = *reinterpret_cast<const float2*>(row + 8);
        acc[0] += wgt * v0.x; acc[1] += wgt * v0.y; acc[2] += wgt * v0.z; acc[3] += wgt * v0.w;
        acc[4] += wgt * v1.x; acc[5] += wgt * v1.y; acc[6] += wgt * v1.z; acc[7] += wgt * v1.w;
        acc[8] += wgt * v2.x; acc[9] += wgt * v2.y;
    }
    float inv = 1.f / (s + 1e-16f);
    float logit[10];
    float mx = -INFINITY;
#pragma unroll
    for (int c = 0; c < 10; c++) {
        logit[c] = acc[c] * inv + bias[c];
        mx = fmaxf(mx, logit[c]);
    }
    float se = 0.f;
#pragma unroll
    for (int c = 0; c < 10; c++) se += __expf(logit[c] - mx);
    float lse = logf(se) + mx;
#pragma unroll
    for (int c = 0; c < 10; c++) out[(size_t)d * 10 + c] = logit[c] - lse;
}

// ---------------------------------------------------------------------------
// Launcher. CSR build on side stream overlapping GEMM1 (4th-created: ncu).
// ---------------------------------------------------------------------------
extern "C" void kernel_launch(void* const* d_in, const int* in_sizes, int n_in,
                              void* d_out, int out_size) {
    const float* x   = (const float*)d_in[0];
    const void*  ei  = d_in[1];
    const float* W1 = (const float*)d_in[2];
    const float* a1s = (const float*)d_in[3];
    const float* a1d = (const float*)d_in[4];
    const float* b1 = (const float*)d_in[5];
    const float* W2 = (const float*)d_in[6];
    const float* a2s = (const float*)d_in[7];
    const float* a2d = (const float*)d_in[8];
    const float* b2 = (const float*)d_in[9];
    const float* W3 = (const float*)d_in[10];
    const float* a3s = (const float*)d_in[11];
    const float* a3d = (const float*)d_in[12];
    const float* b3 = (const float*)d_in[13];
    float* out = (float*)d_out;

    int N = in_sizes[0] / 256;
    int E = in_sizes[1] / 2;
    int nb = (N + 255) / 256;

    static cudaStream_t s_side = nullptr;
    static cudaEvent_t ev_fork = nullptr, ev_join = nullptr;
    if (!s_side) {
        cudaStreamCreateWithFlags(&s_side, cudaStreamNonBlocking);
        cudaEventCreateWithFlags(&ev_fork, cudaEventDisableTiming);
        cudaEventCreateWithFlags(&ev_join, cudaEventDisableTiming);
    }

    constexpr int SMEM1 = (2 * 128 * 36 + 2 * 32 * (128 + 8) + 2 * 128) * 4;
    constexpr int SMEM2 = (2 * 128 * 36 + 2 * 32 * (64 + 8) + 2 * 64) * 4;
    cudaFuncSetAttribute((const void*)gemm_mma_kernel<256, 128, 8, 16, false, 0>,
                         cudaFuncAttributeMaxDynamicSharedMemorySize, SMEM1);
    cudaFuncSetAttribute((const void*)gemm_mma_kernel<128, 64, 8, 8, true, 8>,
                         cudaFuncAttributeMaxDynamicSharedMemorySize, SMEM2);

    int warp_blocks = (N + 7) / 8;
    int gemm_blocks = (N + 127) / 128;

    // Fork: CSR build on side stream, GEMM1 on main stream.
    cudaEventRecord(ev_fork, 0);
    cudaStreamWaitEvent(s_side, ev_fork, 0);

    convert_hist_kernel<<<(E + 255) / 256, 256, 0, s_side>>>(ei, E, N);       // 1
    scan_blocks_kernel<<<nb, 256, 0, s_side>>>(N);                            // 2
    scan_top_kernel<<<1, 1024, 0, s_side>>>(nb, N);                           // 3
    gemm_mma_kernel<256, 128, 8, 16, false, 0><<<gemm_blocks, 256, SMEM1>>>(  // 4 (main)
        x, W1, a1s, a1d, N);
    scan_add_seed_kernel<<<nb, 256, 0, s_side>>>(N);                          // 5
    scatter_kernel<<<(E + 255) / 256, 256, 0, s_side>>>(E);                   // 6
    cudaEventRecord(ev_join, s_side);
    cudaStreamWaitEvent(0, ev_join, 0);

    aggregate1_kernel<<<warp_blocks, 256>>>(b1, N);                           // 7

    gemm_mma_kernel<128, 64, 8, 8, true, 8><<<gemm_blocks, 256, SMEM2>>>(     // 8
        nullptr, W2, a2s, a2d, N);
    aggregate2_fused_kernel<<<warp_blocks, 256>>>(b2, W3, a3s, a3d, N);       // 9
    aggregate3_kernel<<<(N + 255) / 256, 256>>>(b3, out, N);                  // 10
}